// round 6
// baseline (speedup 1.0000x reference)
#include <cuda_runtime.h>

#define TT 512
#define BB 256
#define II 64
#define NN 512
#define NB (BB*NN)
#define NBLK 444

__device__ __align__(256) float g_Wc0[576 * NN];
__device__ __align__(256) float g_Wc1[1088 * NN];
__device__ __align__(256) float g_Wc2[1088 * NN];
__device__ __align__(256) float g_bc[3 * NN];
__device__ __align__(256) float g_S[2][3][NB];
__device__ __align__(256) float g_P[416 * 4096];
__device__ __align__(256) unsigned g_barv[64];   // [0]=cnt (line 0), [32]=gen (line 1)

__device__ __forceinline__ unsigned long long bcast2(float x) {
    unsigned long long r;
    asm("mov.b64 %0,{%1,%1};" : "=l"(r) : "f"(x));
    return r;
}
__device__ __forceinline__ void fma2(unsigned long long& c, unsigned long long a,
                                     unsigned long long b) {
    asm("fma.rn.f32x2 %0,%1,%2,%0;" : "+l"(c) : "l"(a), "l"(b));
}
__device__ __forceinline__ float2 upk(unsigned long long v) {
    float2 f;
    asm("mov.b64 {%0,%1},%2;" : "=f"(f.x), "=f"(f.y) : "l"(v));
    return f;
}
__device__ __forceinline__ void cpa16(float* s, const float* g) {
    unsigned ss = (unsigned)__cvta_generic_to_shared(s);
    asm volatile("cp.async.cg.shared.global [%0],[%1],16;\n" ::"r"(ss), "l"(g));
}

// Grid barrier: 444 co-resident blocks (3/SM guaranteed by launch_bounds+smem).
// Arrivals: one RMW each. Pollers: ld.acquire.gpu (no atomic-ALU serialization).
__device__ __forceinline__ void gridbar(unsigned& gen) {
    __syncthreads();
    if (threadIdx.x == 0) {
        __threadfence();
        unsigned g = gen;
        if (atomicAdd(&g_barv[0], 1u) == NBLK - 1u) {
            atomicExch(&g_barv[0], 0u);
            __threadfence();
            asm volatile("st.release.gpu.b32 [%0],%1;" ::"l"(g_barv + 32), "r"(g + 1u) : "memory");
        } else {
            unsigned v;
            do {
                asm volatile("ld.acquire.gpu.b32 %0,[%1];" : "=r"(v) : "l"(g_barv + 32) : "memory");
            } while (v == g);
        }
    }
    gen++;
    __syncthreads();
}

__global__ void __launch_bounds__(128, 3) persist_kernel(
    const float* __restrict__ data, const float* __restrict__ h0,
    const float* __restrict__ Win, const float* __restrict__ b_in,
    const float* __restrict__ Whh, const float* __restrict__ b_hh,
    const float* __restrict__ Whi, const float* __restrict__ b_hi,
    const float* __restrict__ Wfc, const float* __restrict__ bfc,
    float* __restrict__ out) {
    __shared__ float As[2][64 * 36];
    __shared__ float Bs[2][32 * 64];

    const int tid = threadIdx.x;
    const int jid = blockIdx.x;
    unsigned gen = 0;
    if (tid == 0) gen = *(volatile unsigned*)(g_barv + 32);

    // ---- prep: concat weights, folded biases, init both state buffers ----
    {
        int gt = jid * 128 + tid;
        const int gs = NBLK * 128;
        for (int i = gt; i < 576 * NN; i += gs) {
            int k = i >> 9, n = i & 511;
            g_Wc0[i] = (k < 512) ? ((k == n) ? 0.f : Whh[k * 512 + n])
                                 : Win[(k - 512) * 512 + n];
        }
        for (int i = gt; i < 1088 * NN; i += gs) {
            int k = i >> 9, n = i & 511;
            float v;
            if (k < 512)       v = (k == n) ? 0.f : Whh[(512 + k) * 512 + n];
            else if (k < 1024) v = Whi[(k - 512) * 512 + n];
            else               v = Win[(k - 1024) * 512 + n];
            g_Wc1[i] = v;
        }
        for (int i = gt; i < 1088 * NN; i += gs) {
            int k = i >> 9, n = i & 511;
            float v;
            if (k < 512)       v = (k == n) ? 0.f : Whh[(1024 + k) * 512 + n];
            else if (k < 1024) v = Whi[(512 + (k - 512)) * 512 + n];
            else               v = Win[(k - 1024) * 512 + n];
            g_Wc2[i] = v;
        }
        for (int i = gt; i < 3 * NN; i += gs) {
            int l = i >> 9, n = i & 511;
            float v = b_hh[i] + b_in[n];
            if (l > 0) v += b_hi[(l - 1) * 512 + n];
            g_bc[i] = v;
        }
        for (int i = gt; i < 3 * NB; i += gs) {
            float v = h0[i];
            __stcg(&(&g_S[0][0][0])[i], v);
            __stcg(&(&g_S[1][0][0])[i], v);
        }
    }
    gridbar(gen);

    // ---- gemm job decode (fixed per block) ----
    // heavy: 2 layers x 32 tiles x 5 K-splits (224,224,224,224,192) = 320 jobs
    // light: 32 tiles x 3 K-splits (192 each) = 96 jobs; jid>=416 idle
    int l = 0, tile = 0, k0 = 0, nck = 0;
    const bool hasjob = (jid < 416);
    if (jid < 320) {
        l = 1 + jid / 160;
        int r = jid % 160;
        tile = r / 5;
        int s = r % 5;
        k0 = s * 224; nck = (s == 4) ? 6 : 7;
    } else if (hasjob) {
        int r = jid - 320;
        l = 0; tile = r / 3;
        k0 = (r % 3) * 192; nck = 6;
    }
    const int row0 = (tile >> 3) * 64, col0 = (tile & 7) * 64;
    const float* Wc = (l == 0) ? g_Wc0 : ((l == 1) ? g_Wc1 : g_Wc2);
    const int dbase = l ? 1024 : 512;
    const int tx = tid & 7, ty = tid >> 3;

    // ---- combine job decode: 192 blocks, half a 64x64 tile each ----
    int cl = 0, ctile = 0, cj0 = 0, cnsp = 0, chalf = 0;
    if (jid < 128) {
        cl = 1 + (jid >> 6);
        int r = jid & 63;
        ctile = r >> 1; chalf = r & 1;
        cj0 = (cl - 1) * 160 + ctile * 5; cnsp = 5;
    } else if (jid < 192) {
        int r = jid - 128;
        cl = 0; ctile = r >> 1; chalf = r & 1;
        cj0 = 320 + ctile * 3; cnsp = 3;
    }
    const int crow0 = (ctile >> 3) * 64, ccol0 = (ctile & 7) * 64;

    // ---- wavefront ticks ----
    for (int kk = 0; kk < TT + 2; kk++) {
        const int cur = kk & 1, prev = cur ^ 1;
        const int t = kk - l;
        if (hasjob && t >= 0 && t < TT) {
            unsigned long long acc[4][4];
#pragma unroll
            for (int m = 0; m < 4; m++)
#pragma unroll
                for (int j = 0; j < 4; j++) acc[m][j] = 0ull;

            auto load_chunk = [&](int ci, int buf) {
                int kabs = k0 + ci * 32;
                const float* src;
                int sA;
                if (kabs < 512)                { src = &g_S[prev][l][kabs];           sA = NN; }
                else if (l > 0 && kabs < 1024) { src = &g_S[prev][l - 1][kabs - 512]; sA = NN; }
                else { src = data + (size_t)t * (BB * II) + (kabs - dbase);           sA = II; }
                src += (size_t)row0 * sA;
#pragma unroll
                for (int i = 0; i < 4; i++) {
                    int u = tid * 4 + i;
                    int r = u >> 3, q = (u & 7) * 4;
                    cpa16(&As[buf][r * 36 + q], src + (size_t)r * sA + q);
                }
                const float* wsrc = Wc + (size_t)kabs * NN + col0;
#pragma unroll
                for (int i = 0; i < 4; i++) {
                    int u = tid * 4 + i;
                    int r = u >> 4, q = (u & 15) * 4;
                    cpa16(&Bs[buf][r * 64 + q], wsrc + (size_t)r * NN + q);
                }
                asm volatile("cp.async.commit_group;\n");
            };

            load_chunk(0, 0);
            for (int ci = 0; ci < nck; ci++) {
                int buf = ci & 1;
                if (ci + 1 < nck) {
                    load_chunk(ci + 1, buf ^ 1);
                    asm volatile("cp.async.wait_group 1;\n");
                } else {
                    asm volatile("cp.async.wait_group 0;\n");
                }
                __syncthreads();
                const float* A = As[buf];
                const float* Bp = Bs[buf];
#pragma unroll 8
                for (int k = 0; k < 32; k++) {
                    // B: 8 contiguous cols per thread -> 2x LDS.128
                    ulonglong2 Bq0 = *(const ulonglong2*)&Bp[k * 64 + tx * 8];
                    ulonglong2 Bq1 = *(const ulonglong2*)&Bp[k * 64 + tx * 8 + 4];
#pragma unroll
                    for (int m = 0; m < 4; m++) {
                        unsigned long long ap = bcast2(A[(ty + 16 * m) * 36 + k]);
                        fma2(acc[m][0], ap, Bq0.x);
                        fma2(acc[m][1], ap, Bq0.y);
                        fma2(acc[m][2], ap, Bq1.x);
                        fma2(acc[m][3], ap, Bq1.y);
                    }
                }
                __syncthreads();
            }
            float* P = &g_P[(size_t)jid * 4096];
#pragma unroll
            for (int m = 0; m < 4; m++)
#pragma unroll
                for (int j = 0; j < 4; j++) {
                    float2 v = upk(acc[m][j]);
                    *(float2*)&P[(ty + 16 * m) * 64 + tx * 8 + j * 2] = v;
                }
        }
        gridbar(gen);

        // combine: sum K-split partials + leaky-integrate + LeakyReLU
        if (jid < 192) {
            const int ct = kk - cl;
            if (ct >= 0 && ct < TT) {
                const float4* P0 = (const float4*)&g_P[(size_t)cj0 * 4096];
                const float* hold = g_S[prev][cl];
                float* dst = g_S[cur][cl];
                const float* bias = &g_bc[cl * NN];
                const int base = chalf * 512;
                for (int i = tid; i < 512; i += 128) {
                    int ii = base + i;
                    float4 s = __ldcg(&P0[ii]);
                    for (int sp = 1; sp < cnsp; sp++) {
                        float4 sx = __ldcg(&P0[sp * 1024 + ii]);
                        s.x += sx.x; s.y += sx.y; s.z += sx.z; s.w += sx.w;
                    }
                    int e = ii * 4;
                    int gr = crow0 + (e >> 6), gc = ccol0 + (e & 63);
                    float4 h = __ldcg((const float4*)&hold[gr * NN + gc]);
                    float4 b = *(const float4*)&bias[gc];
                    float4 o;
                    o.x = 0.5f * h.x + 0.5f * (s.x + b.x);
                    o.y = 0.5f * h.y + 0.5f * (s.y + b.y);
                    o.z = 0.5f * h.z + 0.5f * (s.z + b.z);
                    o.w = 0.5f * h.w + 0.5f * (s.w + b.w);
                    o.x = (o.x > 0.f) ? o.x : 0.01f * o.x;
                    o.y = (o.y > 0.f) ? o.y : 0.01f * o.y;
                    o.z = (o.z > 0.f) ? o.z : 0.01f * o.z;
                    o.w = (o.w > 0.f) ? o.w : 0.01f * o.w;
                    __stcg((float4*)&dst[gr * NN + gc], o);
                }
            }
        }
        gridbar(gen);
    }

    // ---- readout: 2560 dot products, one warp each ----
    {
        int warp0 = jid * 4 + (tid >> 5);
        int lane = tid & 31;
        for (int gw = warp0; gw < BB * 10; gw += NBLK * 4) {
            int b = gw / 10, c = gw % 10;
            const float* h = &g_S[1][2][b * NN];
            float s = 0.f;
            for (int k = lane; k < NN; k += 32)
                s += __ldcg(&h[k]) * Wfc[k * 10 + c];
#pragma unroll
            for (int o = 16; o; o >>= 1) s += __shfl_down_sync(0xffffffffu, s, o);
            if (lane == 0) out[b * 10 + c] = s + bfc[c];
        }
    }
}

extern "C" void kernel_launch(void* const* d_in, const int* in_sizes, int n_in,
                              void* d_out, int out_size) {
    const float* data = (const float*)d_in[0];
    const float* h0   = (const float*)d_in[1];
    const float* Win  = (const float*)d_in[2];
    const float* b_in = (const float*)d_in[3];
    const float* Whh  = (const float*)d_in[4];
    const float* b_hh = (const float*)d_in[5];
    const float* Whi  = (const float*)d_in[6];
    const float* b_hi = (const float*)d_in[7];
    const float* Wfc  = (const float*)d_in[8];
    const float* b_fc = (const float*)d_in[9];
    float* out = (float*)d_out;

    persist_kernel<<<NBLK, 128>>>(data, h0, Win, b_in, Whh, b_hh, Whi, b_hi,
                                  Wfc, b_fc, out);
}